// round 13
// baseline (speedup 1.0000x reference)
#include <cuda_runtime.h>
#include <math.h>

#define NB 256      // batch
#define CC 256      // channels
#define TT 64       // time
#define VV 25       // vertices
#define DD 10       // final SPD dim
#define OUTD 64
#define FEATD 100
#define NS 65       // 10 mean-sums + 55 gram upper-tri
#define BPS 32      // blocks per sample in kernel 1

// scratch (allocation-free rule). Non-atomic per-block partials, transposed
// layout [sample][sum][block] so the reducer reads contiguous float4s.
// Every element rewritten every launch -> no zeroing, graph-deterministic.
__device__ float g_P[NB * NS * BPS];     // 2.1 MB, L2-resident

// ---------------------------------------------------------------------------
// Kernel 1: per (n,c) row: temporal mean, project through Wc = W1@W2@W3,
// then block-local reduction of 8 rows' mean/Gram partials -> 65 stores.
// Streaming loop unchanged (at DRAM floor).
// ---------------------------------------------------------------------------
__global__ void __launch_bounds__(256)
meanproj_kernel(const float* __restrict__ x,
                const float* __restrict__ W1,
                const float* __restrict__ W2,
                const float* __restrict__ W3) {
    __shared__ float t15[VV * 15];
    __shared__ float sWc[VV * DD + 32];   // padded so lanes>=10 read safely
    __shared__ float sy8[8][DD];          // this block's 8 projected vectors

    const int tid = threadIdx.x;

    for (int e = tid; e < VV * 15; e += 256) {
        int i = e / 15, j = e % 15;
        float s = 0.f;
        #pragma unroll
        for (int k = 0; k < 20; k++) s += W1[i * 20 + k] * W2[k * 15 + j];
        t15[e] = s;
    }
    __syncthreads();
    for (int e = tid; e < VV * DD + 32; e += 256) {
        float s = 0.f;
        if (e < VV * DD) {
            int i = e / DD, j = e % DD;
            #pragma unroll
            for (int k = 0; k < 15; k++) s += t15[i * 15 + k] * W3[k * DD + j];
        }
        sWc[e] = s;
    }
    __syncthreads();

    const int warp = tid >> 5, lane = tid & 31;
    const int gw = blockIdx.x * 8 + warp;           // (n,c) row index

    float xm = 0.f;
    if (lane < VV) {
        const float* p = x + (size_t)gw * (TT * VV) + lane;
        float a0 = 0.f, a1 = 0.f, a2 = 0.f, a3 = 0.f;
        float a4 = 0.f, a5 = 0.f, a6 = 0.f, a7 = 0.f;
        #pragma unroll
        for (int t = 0; t < TT; t += 8) {
            a0 += __ldcs(&p[(t + 0) * VV]);
            a1 += __ldcs(&p[(t + 1) * VV]);
            a2 += __ldcs(&p[(t + 2) * VV]);
            a3 += __ldcs(&p[(t + 3) * VV]);
            a4 += __ldcs(&p[(t + 4) * VV]);
            a5 += __ldcs(&p[(t + 5) * VV]);
            a6 += __ldcs(&p[(t + 6) * VV]);
            a7 += __ldcs(&p[(t + 7) * VV]);
        }
        xm = (((a0 + a1) + (a2 + a3)) + ((a4 + a5) + (a6 + a7))) * (1.0f / TT);
    }

    float y = 0.f;
    #pragma unroll
    for (int v = 0; v < VV; v++) {
        float xv = __shfl_sync(0xffffffffu, xm, v);
        y += xv * sWc[v * DD + lane];               // lanes >=10 hit pad
    }
    if (lane < DD) sy8[warp][lane] = y;
    __syncthreads();

    // block-local partials -> 65 global stores (transposed layout)
    if (tid < NS) {
        float s;
        if (tid < DD) {
            s = 0.f;
            #pragma unroll
            for (int c = 0; c < 8; c++) s += sy8[c][tid];
        } else {
            int e = tid - DD, p = 0;
            while (e >= DD - p) { e -= DD - p; p++; }
            int q = p + e;
            s = 0.f;
            #pragma unroll
            for (int c = 0; c < 8; c++) s += sy8[c][p] * sy8[c][q];
        }
        const int n = blockIdx.x >> 5;              // 32 blocks per sample
        const int b = blockIdx.x & 31;
        g_P[((size_t)n * NS + tid) * BPS + b] = s;
    }
}

// row (registers) x matrix (smem, rows padded to 16 floats) -> nP
__device__ __forceinline__ void rowmul(const float* __restrict__ sM,
                                       const float* Prow, float* nP) {
    #pragma unroll
    for (int j = 0; j < DD; j++) nP[j] = 0.f;
    #pragma unroll
    for (int t = 0; t < DD; t++) {
        const float pv = Prow[t];
        const float4* er = (const float4*)&sM[t * 16];
        float4 e0 = er[0], e1 = er[1], e2 = er[2];
        nP[0] += pv * e0.x; nP[1] += pv * e0.y;
        nP[2] += pv * e0.z; nP[3] += pv * e0.w;
        nP[4] += pv * e1.x; nP[5] += pv * e1.y;
        nP[6] += pv * e1.z; nP[7] += pv * e1.w;
        nP[8] += pv * e2.x; nP[9] += pv * e2.y;
    }
}

// ---------------------------------------------------------------------------
// Kernel 2: ONE WARP per sample: reduce 32 partials (contiguous float4 from
// L2), build E = A/s - I with s = tr(A)/10, then degree-12 Mercator log via
// Paterson-Stockmeyer (5 matmuls, chain of 4), FC.
// ALL 32 lanes execute the series on a clamped row index (li); only lanes
// < DD store to shared. Every __syncwarp() is convergent (full warp).
// ---------------------------------------------------------------------------
__global__ void __launch_bounds__(32)
spd_kernel(const float* __restrict__ fcw, const float* __restrict__ fcb,
           float* __restrict__ out) {
    __shared__ float sS [NS];
    __shared__ float sE [DD * 16];
    __shared__ float sE2[DD * 16];
    __shared__ float sE4[DD * 16];
    __shared__ float sL [FEATD];

    const int n    = blockIdx.x;
    const int lane = threadIdx.x;

    // lane l reduces sums {l, l+32, l+64}: 8 consecutive float4 loads each
    #pragma unroll
    for (int h = 0; h < 3; h++) {
        const int i = lane + h * 32;
        if (i < NS) {
            const float4* p4 = (const float4*)&g_P[((size_t)n * NS + i) * BPS];
            float s = 0.f;
            #pragma unroll
            for (int b = 0; b < BPS / 4; b++) {
                float4 v = p4[b];
                s += (v.x + v.y) + (v.z + v.w);
            }
            sS[i] = s;
        }
    }
    __syncwarp();

    // s = tr(A)/10 (all lanes redundantly); A = (G - C m m^T)/(C-1) + 1e-8 I
    float s_tr = 0.f;
    #pragma unroll
    for (int i = 0; i < DD; i++) {
        int idx = DD + 10 * i - (i * (i - 1)) / 2;
        float mi = sS[i] * (1.0f / CC);
        s_tr += sS[idx] - (float)CC * mi * mi;
    }
    s_tr = s_tr * (1.0f / (CC - 1)) * 0.1f + 1e-8f;
    const float inv_s = __fdividef(1.f, s_tr);
    const float logs  = __logf(s_tr);

    // build row li of E = A/s - I (all lanes; lanes>=10 clamp to row 0)
    const int li = (lane < DD) ? lane : 0;
    float Erow[DD];
    {
        const float mi = sS[li] * (1.0f / CC);
        #pragma unroll
        for (int j = 0; j < DD; j++) {
            int p = li < j ? li : j;
            int q = li < j ? j : li;
            int idx = DD + 10 * p - (p * (p - 1)) / 2 + (q - p);
            float mj = sS[j] * (1.0f / CC);
            float a = (sS[idx] - (float)CC * mi * mj) * (1.0f / (CC - 1))
                    + ((li == j) ? 1e-8f : 0.f);
            Erow[j] = a * inv_s - ((li == j) ? 1.f : 0.f);
        }
    }
    if (lane < DD) {
        #pragma unroll
        for (int j = 0; j < DD; j++) sE[lane * 16 + j] = Erow[j];
    }
    __syncwarp();

    // ---- Paterson-Stockmeyer, degree 12, F = E^4:
    //   p(E) = C0 + C1 F + C2 F^2 + c12 F^3,
    //   Cm = c4m I + c4m+1 E + c4m+2 E^2 + c4m+3 E^3,  ck = (-1)^{k+1}/k
    const float c1 = 1.f,        c2 = -0.5f,       c3 = 1.f / 3.f;
    const float c4 = -0.25f,     c5 = 0.2f,        c6 = -1.f / 6.f;
    const float c7 = 1.f / 7.f,  c8 = -0.125f,     c9 = 1.f / 9.f;
    const float c10 = -0.1f,     c11 = 1.f / 11.f, c12 = -1.f / 12.f;

    float E2row[DD], E3row[DD], E4row[DD], R[DD], T[DD];
    rowmul(sE, Erow, E2row);                      // E^2
    if (lane < DD) {
        #pragma unroll
        for (int j = 0; j < DD; j++) sE2[lane * 16 + j] = E2row[j];
    }
    __syncwarp();
    rowmul(sE,  E2row, E3row);                    // E^3 = E^2 * E
    rowmul(sE2, E2row, E4row);                    // E^4 = E^2 * E^2 (ILP)
    if (lane < DD) {
        #pragma unroll
        for (int j = 0; j < DD; j++) sE4[lane * 16 + j] = E4row[j];
    }
    __syncwarp();

    // R = c12*F + C2
    #pragma unroll
    for (int j = 0; j < DD; j++)
        R[j] = c12 * E4row[j] + c9 * Erow[j] + c10 * E2row[j]
             + c11 * E3row[j] + ((li == j) ? c8 : 0.f);
    // R = R*F + C1
    rowmul(sE4, R, T);
    #pragma unroll
    for (int j = 0; j < DD; j++)
        R[j] = T[j] + c5 * Erow[j] + c6 * E2row[j] + c7 * E3row[j]
             + ((li == j) ? c4 : 0.f);
    // R = R*F + C0
    rowmul(sE4, R, T);
    #pragma unroll
    for (int j = 0; j < DD; j++)
        R[j] = T[j] + c1 * Erow[j] + c2 * E2row[j] + c3 * E3row[j];

    if (lane < DD) {
        #pragma unroll
        for (int j = 0; j < DD; j++)
            sL[lane * DD + j] = R[j] + ((li == j) ? logs : 0.f);
    }
    __syncwarp();

    // FC: each lane computes outputs m = lane and lane+32
    #pragma unroll
    for (int h = 0; h < 2; h++) {
        const int mo = lane + h * 32;
        float s = fcb[mo];
        const float* wr = fcw + mo * FEATD;
        #pragma unroll 5
        for (int f = 0; f < FEATD; f++) s += sL[f] * wr[f];
        out[n * OUTD + mo] = s;
    }
}

// ---------------------------------------------------------------------------
extern "C" void kernel_launch(void* const* d_in, const int* in_sizes, int n_in,
                              void* d_out, int out_size) {
    const float *x = nullptr, *W1 = nullptr, *W2 = nullptr, *W3 = nullptr;
    const float *fcw = nullptr, *fcb = nullptr;
    for (int i = 0; i < n_in; i++) {
        switch (in_sizes[i]) {
            case NB * CC * TT * VV: x   = (const float*)d_in[i]; break;
            case 500:               W1  = (const float*)d_in[i]; break;
            case 300:               W2  = (const float*)d_in[i]; break;
            case 150:               W3  = (const float*)d_in[i]; break;
            case 6400:              fcw = (const float*)d_in[i]; break;
            case 64:                fcb = (const float*)d_in[i]; break;
            default: break;
        }
    }

    // one warp per (n,c) row: 65536 rows -> 8192 blocks x 8 warps
    meanproj_kernel<<<(NB * CC) / 8, 256>>>(x, W1, W2, W3);

    // one warp per sample
    spd_kernel<<<NB, 32>>>(fcw, fcb, (float*)d_out);
}

// round 16
// speedup vs baseline: 1.5052x; 1.5052x over previous
#include <cuda_runtime.h>
#include <math.h>

#define NB 256      // batch
#define CC 256      // channels
#define TT 64       // time
#define VV 25       // vertices
#define DD 10       // final SPD dim
#define OUTD 64
#define FEATD 100
#define NS 65       // 10 mean-sums + 55 gram upper-tri
#define BPS 32      // blocks per sample in kernel 1

// scratch (allocation-free rule). Coalesced per-block partials [block][NS].
// Every element rewritten every launch -> no zeroing, graph-deterministic.
__device__ float g_P[NB * BPS * NS];     // 2.1 MB, L2-resident

// ---------------------------------------------------------------------------
// Kernel 1: per (n,c) row: temporal mean, project through Wc = W1@W2@W3,
// then block-local reduction of 8 rows' mean/Gram partials -> 65 coalesced
// stores. Streaming loop unchanged (at DRAM floor).
// ---------------------------------------------------------------------------
__global__ void __launch_bounds__(256)
meanproj_kernel(const float* __restrict__ x,
                const float* __restrict__ W1,
                const float* __restrict__ W2,
                const float* __restrict__ W3) {
    __shared__ float t15[VV * 15];
    __shared__ float sWc[VV * DD + 32];   // padded so lanes>=10 read safely
    __shared__ float sy8[8][DD];          // this block's 8 projected vectors

    const int tid = threadIdx.x;

    for (int e = tid; e < VV * 15; e += 256) {
        int i = e / 15, j = e % 15;
        float s = 0.f;
        #pragma unroll
        for (int k = 0; k < 20; k++) s += W1[i * 20 + k] * W2[k * 15 + j];
        t15[e] = s;
    }
    __syncthreads();
    for (int e = tid; e < VV * DD + 32; e += 256) {
        float s = 0.f;
        if (e < VV * DD) {
            int i = e / DD, j = e % DD;
            #pragma unroll
            for (int k = 0; k < 15; k++) s += t15[i * 15 + k] * W3[k * DD + j];
        }
        sWc[e] = s;
    }
    __syncthreads();

    const int warp = tid >> 5, lane = tid & 31;
    const int gw = blockIdx.x * 8 + warp;           // (n,c) row index

    float xm = 0.f;
    if (lane < VV) {
        const float* p = x + (size_t)gw * (TT * VV) + lane;
        float a0 = 0.f, a1 = 0.f, a2 = 0.f, a3 = 0.f;
        float a4 = 0.f, a5 = 0.f, a6 = 0.f, a7 = 0.f;
        #pragma unroll
        for (int t = 0; t < TT; t += 8) {
            a0 += __ldcs(&p[(t + 0) * VV]);
            a1 += __ldcs(&p[(t + 1) * VV]);
            a2 += __ldcs(&p[(t + 2) * VV]);
            a3 += __ldcs(&p[(t + 3) * VV]);
            a4 += __ldcs(&p[(t + 4) * VV]);
            a5 += __ldcs(&p[(t + 5) * VV]);
            a6 += __ldcs(&p[(t + 6) * VV]);
            a7 += __ldcs(&p[(t + 7) * VV]);
        }
        xm = (((a0 + a1) + (a2 + a3)) + ((a4 + a5) + (a6 + a7))) * (1.0f / TT);
    }

    float y = 0.f;
    #pragma unroll
    for (int v = 0; v < VV; v++) {
        float xv = __shfl_sync(0xffffffffu, xm, v);
        y += xv * sWc[v * DD + lane];               // lanes >=10 hit pad
    }
    if (lane < DD) sy8[warp][lane] = y;
    __syncthreads();

    // block-local partials -> 65 coalesced global stores
    if (tid < NS) {
        float s;
        if (tid < DD) {
            s = 0.f;
            #pragma unroll
            for (int c = 0; c < 8; c++) s += sy8[c][tid];
        } else {
            int e = tid - DD, p = 0;
            while (e >= DD - p) { e -= DD - p; p++; }
            int q = p + e;
            s = 0.f;
            #pragma unroll
            for (int c = 0; c < 8; c++) s += sy8[c][p] * sy8[c][q];
        }
        g_P[blockIdx.x * NS + tid] = s;
    }
}

// row (registers) x matrix (smem, rows padded to 16 floats, 16B-aligned)
__device__ __forceinline__ void rowmul(const float* __restrict__ sM,
                                       const float* Prow, float* nP) {
    #pragma unroll
    for (int j = 0; j < DD; j++) nP[j] = 0.f;
    #pragma unroll
    for (int t = 0; t < DD; t++) {
        const float pv = Prow[t];
        const float4* er = (const float4*)&sM[t * 16];
        float4 e0 = er[0], e1 = er[1], e2 = er[2];
        nP[0] += pv * e0.x; nP[1] += pv * e0.y;
        nP[2] += pv * e0.z; nP[3] += pv * e0.w;
        nP[4] += pv * e1.x; nP[5] += pv * e1.y;
        nP[6] += pv * e1.z; nP[7] += pv * e1.w;
        nP[8] += pv * e2.x; nP[9] += pv * e2.y;
    }
}

// ---------------------------------------------------------------------------
// Kernel 2: 128 blocks x 64 threads = 2 samples/block (one warp each), ONE
// wave. fcw/fcb preloaded to smem cooperatively. Per warp: reduce 32
// partials, E = A/s - I, degree-12 Mercator log via Paterson-Stockmeyer
// (5 matmuls), FC from smem. All float4-accessed shared arrays __align__(16).
// ---------------------------------------------------------------------------
__global__ void __launch_bounds__(64)
spd_kernel(const float* __restrict__ fcw, const float* __restrict__ fcb,
           float* __restrict__ out) {
    __shared__ __align__(16) float sF [OUTD * FEATD];   // 25.6 KB
    __shared__ __align__(16) float sE [2][DD * 16];
    __shared__ __align__(16) float sE2[2][DD * 16];
    __shared__ __align__(16) float sE4[2][DD * 16];
    __shared__ float sB [OUTD];
    __shared__ float sS [2][NS];
    __shared__ float sL [2][FEATD];

    const int tid  = threadIdx.x;
    const int wid  = tid >> 5;
    const int lane = tid & 31;
    const int n    = blockIdx.x * 2 + wid;

    // cooperative FC-weight preload (1600 float4, 25 per thread, MLP-rich)
    {
        float4* d4 = (float4*)sF;
        const float4* s4 = (const float4*)fcw;
        #pragma unroll
        for (int e = tid; e < OUTD * FEATD / 4; e += 64) d4[e] = s4[e];
        if (tid < OUTD) sB[tid] = fcb[tid];
    }

    // ---- per-warp: reduce this sample's 32 partial records ----
    const float* gp = g_P + (size_t)n * BPS * NS;
    #pragma unroll
    for (int h = 0; h < 3; h++) {
        const int i = lane + h * 32;
        if (i < NS) {
            float s = 0.f;
            #pragma unroll
            for (int b = 0; b < BPS; b++) s += gp[b * NS + i];
            sS[wid][i] = s;
        }
    }
    __syncwarp();

    // s = tr(A)/10 (all lanes redundantly); A = (G - C m m^T)/(C-1) + 1e-8 I
    float s_tr = 0.f;
    #pragma unroll
    for (int i = 0; i < DD; i++) {
        int idx = DD + 10 * i - (i * (i - 1)) / 2;
        float mi = sS[wid][i] * (1.0f / CC);
        s_tr += sS[wid][idx] - (float)CC * mi * mi;
    }
    s_tr = s_tr * (1.0f / (CC - 1)) * 0.1f + 1e-8f;
    const float inv_s = __fdividef(1.f, s_tr);
    const float logs  = __logf(s_tr);

    // build row li of E = A/s - I (all lanes; lanes>=10 clamp to row 0)
    const int li = (lane < DD) ? lane : 0;
    float Erow[DD];
    {
        const float mi = sS[wid][li] * (1.0f / CC);
        #pragma unroll
        for (int j = 0; j < DD; j++) {
            int p = li < j ? li : j;
            int q = li < j ? j : li;
            int idx = DD + 10 * p - (p * (p - 1)) / 2 + (q - p);
            float mj = sS[wid][j] * (1.0f / CC);
            float a = (sS[wid][idx] - (float)CC * mi * mj) * (1.0f / (CC - 1))
                    + ((li == j) ? 1e-8f : 0.f);
            Erow[j] = a * inv_s - ((li == j) ? 1.f : 0.f);
        }
    }
    if (lane < DD) {
        #pragma unroll
        for (int j = 0; j < DD; j++) sE[wid][lane * 16 + j] = Erow[j];
    }
    __syncwarp();

    // ---- Paterson-Stockmeyer, degree 12, F = E^4:
    //   p(E) = C0 + C1 F + C2 F^2 + c12 F^3,
    //   Cm = c4m I + c4m+1 E + c4m+2 E^2 + c4m+3 E^3,  ck = (-1)^{k+1}/k
    const float c1 = 1.f,        c2 = -0.5f,       c3 = 1.f / 3.f;
    const float c4 = -0.25f,     c5 = 0.2f,        c6 = -1.f / 6.f;
    const float c7 = 1.f / 7.f,  c8 = -0.125f,     c9 = 1.f / 9.f;
    const float c10 = -0.1f,     c11 = 1.f / 11.f, c12 = -1.f / 12.f;

    float E2row[DD], E3row[DD], E4row[DD], R[DD], T[DD];
    rowmul(sE[wid], Erow, E2row);                 // E^2
    if (lane < DD) {
        #pragma unroll
        for (int j = 0; j < DD; j++) sE2[wid][lane * 16 + j] = E2row[j];
    }
    __syncwarp();
    rowmul(sE[wid],  E2row, E3row);               // E^3 = E^2 * E
    rowmul(sE2[wid], E2row, E4row);               // E^4 = E^2 * E^2 (ILP)
    if (lane < DD) {
        #pragma unroll
        for (int j = 0; j < DD; j++) sE4[wid][lane * 16 + j] = E4row[j];
    }
    __syncwarp();

    // R = c12*F + C2
    #pragma unroll
    for (int j = 0; j < DD; j++)
        R[j] = c12 * E4row[j] + c9 * Erow[j] + c10 * E2row[j]
             + c11 * E3row[j] + ((li == j) ? c8 : 0.f);
    // R = R*F + C1
    rowmul(sE4[wid], R, T);
    #pragma unroll
    for (int j = 0; j < DD; j++)
        R[j] = T[j] + c5 * Erow[j] + c6 * E2row[j] + c7 * E3row[j]
             + ((li == j) ? c4 : 0.f);
    // R = R*F + C0
    rowmul(sE4[wid], R, T);
    #pragma unroll
    for (int j = 0; j < DD; j++)
        R[j] = T[j] + c1 * Erow[j] + c2 * E2row[j] + c3 * E3row[j];

    if (lane < DD) {
        #pragma unroll
        for (int j = 0; j < DD; j++)
            sL[wid][lane * DD + j] = R[j] + ((li == j) ? logs : 0.f);
    }

    // both warps' preload stores + sL must be visible before FC reads sF
    __syncthreads();

    // ---- FC from smem: each lane computes outputs m = lane and lane+32 ----
    #pragma unroll
    for (int h = 0; h < 2; h++) {
        const int mo = lane + h * 32;
        float s = sB[mo];
        const float* wr = sF + mo * FEATD;
        const float* Lr = sL[wid];
        #pragma unroll 10
        for (int f = 0; f < FEATD; f++) s += Lr[f] * wr[f];
        out[n * OUTD + mo] = s;
    }
}

// ---------------------------------------------------------------------------
extern "C" void kernel_launch(void* const* d_in, const int* in_sizes, int n_in,
                              void* d_out, int out_size) {
    const float *x = nullptr, *W1 = nullptr, *W2 = nullptr, *W3 = nullptr;
    const float *fcw = nullptr, *fcb = nullptr;
    for (int i = 0; i < n_in; i++) {
        switch (in_sizes[i]) {
            case NB * CC * TT * VV: x   = (const float*)d_in[i]; break;
            case 500:               W1  = (const float*)d_in[i]; break;
            case 300:               W2  = (const float*)d_in[i]; break;
            case 150:               W3  = (const float*)d_in[i]; break;
            case 6400:              fcw = (const float*)d_in[i]; break;
            case 64:                fcb = (const float*)d_in[i]; break;
            default: break;
        }
    }

    // one warp per (n,c) row: 65536 rows -> 8192 blocks x 8 warps
    meanproj_kernel<<<(NB * CC) / 8, 256>>>(x, W1, W2, W3);

    // 2 samples per block (one warp each): 128 blocks -> single wave
    spd_kernel<<<NB / 2, 64>>>(fcw, fcb, (float*)d_out);
}